// round 2
// baseline (speedup 1.0000x reference)
#include <cuda_runtime.h>
#include <math.h>

#define N_NODES 100000
#define C 128
#define BN_EPS 1e-5f

// ---------------- persistent device scratch (no allocations; 16B-aligned) ----------------
__device__ float4 g_agg4[(size_t)N_NODES * C / 4];   // 51.2 MB neighbor-sum accumulator
__device__ float  g_cnt[N_NODES];                    // in-degree counts (float)
__device__ float4 g_h0_4[(size_t)N_NODES * C / 4];   // layer ping
__device__ float4 g_h1_4[(size_t)N_NODES * C / 4];   // layer pong
__device__ int    g_is64;                            // edge_index dtype flag

// ---------------- detect edge_index dtype (int64 vs int32) ----------------
__global__ void detect_kernel(const void* __restrict__ ei) {
    const long long* p64 = (const long long*)ei;
    int ok = 1;
    for (int i = 0; i < 64; ++i) {
        long long v = p64[i];
        if (v < 0 || v >= N_NODES) { ok = 0; break; }
    }
    g_is64 = ok;
}

// ---------------- zero agg (and cnt on first layer) ----------------
__global__ void zero_kernel(int zero_cnt) {
    size_t i = (size_t)blockIdx.x * blockDim.x + threadIdx.x;
    size_t n4 = (size_t)N_NODES * C / 4;
    if (i < n4) g_agg4[i] = make_float4(0.f, 0.f, 0.f, 0.f);
    if (zero_cnt && i < N_NODES) g_cnt[i] = 0.f;
}

// ---------------- edge scatter: one warp per edge, float4 vector atomics ----------------
__global__ void scatter_kernel(const float* __restrict__ x_ext, int in_sel,
                               const void* __restrict__ ei,
                               int E, int do_cnt) {
    const float* x = (in_sel == 0) ? x_ext : (in_sel == 1 ? (const float*)g_h0_4
                                                          : (const float*)g_h1_4);
    int w = (int)(((size_t)blockIdx.x * blockDim.x + threadIdx.x) >> 5);
    int lane = threadIdx.x & 31;
    if (w >= E) return;
    int s, d;
    if (g_is64) {
        const long long* p = (const long long*)ei;
        s = (int)p[w];
        d = (int)p[(size_t)E + w];
    } else {
        const int* p = (const int*)ei;
        s = p[w];
        d = p[(size_t)E + w];
    }
    if ((unsigned)s >= N_NODES || (unsigned)d >= N_NODES) return;  // defensive
    float4 v = ((const float4*)(x + (size_t)s * C))[lane];
    atomicAdd(((float4*)g_agg4) + (size_t)d * (C / 4) + lane, v);
    if (do_cnt && lane == 0) atomicAdd(&g_cnt[d], 1.0f);
}

// ---------------- fused: out = (agg/max(cnt,1)) @ Wl + bl + hin @ Wr, then BN (+ Mish) ----
// CTA: 256 threads, 128x128 output tile, K = 256 in chunks of 16, 8x8 per-thread micro-tile.
__global__ __launch_bounds__(256)
void sage_gemm_kernel(const float* __restrict__ hin_ext, int in_sel,
                      float* __restrict__ out_ext, int out_sel,
                      const float* __restrict__ Wl, const float* __restrict__ bl,
                      const float* __restrict__ Wr,
                      const float* __restrict__ gamma, const float* __restrict__ beta,
                      const float* __restrict__ rmean, const float* __restrict__ rvar,
                      int apply_mish) {
    const float* hin = (in_sel == 0) ? hin_ext : (in_sel == 1 ? (const float*)g_h0_4
                                                              : (const float*)g_h1_4);
    float* out = (out_sel == 0) ? out_ext : (out_sel == 1 ? (float*)g_h0_4
                                                          : (float*)g_h1_4);

    __shared__ float As[128 * 16];   // A tile, [m][k] row-major
    __shared__ float Bs[16 * 128];   // W tile, [k][n] row-major
    __shared__ float s_icnt[128];
    __shared__ float s_sc[128];
    __shared__ float s_off[128];

    int t = threadIdx.x;
    int row0 = blockIdx.x * 128;

    if (t < 128) {
        int r = row0 + t;
        s_icnt[t] = (r < N_NODES) ? (1.0f / fmaxf(g_cnt[r], 1.0f)) : 0.0f;
        float sc = gamma[t] * rsqrtf(rvar[t] + BN_EPS);
        s_sc[t] = sc;
        s_off[t] = (bl[t] - rmean[t]) * sc + beta[t];
    }
    __syncthreads();

    int tx = t & 15;   // col group: cols tx*8 .. tx*8+7
    int ty = t >> 4;   // row group: rows ty*8 .. ty*8+7

    float acc[8][8];
#pragma unroll
    for (int i = 0; i < 8; ++i)
#pragma unroll
        for (int j = 0; j < 8; ++j) acc[i][j] = 0.f;

    // A loader: 512 float4 per tile -> 2 per thread
    int a_m = t >> 2;   // 0..63 (and +64)
    int a_c = t & 3;    // float4 column within 16-wide k chunk
    // B loader: 512 float4 per tile -> 2 per thread
    int b_k = t >> 5;   // 0..7 (and +8)
    int b_c = t & 31;   // float4 column within 128-wide row

    for (int kc = 0; kc < 2 * C; kc += 16) {
        bool isAgg = (kc < C);
        const float* Abase = isAgg ? (const float*)g_agg4 : hin;
        const float* Wb    = isAgg ? Wl : Wr;
        int koff = isAgg ? kc : (kc - C);

#pragma unroll
        for (int h = 0; h < 2; ++h) {
            int m = a_m + h * 64;
            int r = row0 + m;
            float4 v = make_float4(0.f, 0.f, 0.f, 0.f);
            if (r < N_NODES) {
                v = *(const float4*)(Abase + (size_t)r * C + koff + a_c * 4);
                if (isAgg) {
                    float ic = s_icnt[m];
                    v.x *= ic; v.y *= ic; v.z *= ic; v.w *= ic;
                }
            }
            *(float4*)(As + m * 16 + a_c * 4) = v;
        }
#pragma unroll
        for (int h = 0; h < 2; ++h) {
            int k = b_k + h * 8;
            float4 v = *(const float4*)(Wb + (size_t)(koff + k) * C + b_c * 4);
            *(float4*)(Bs + k * C + b_c * 4) = v;
        }
        __syncthreads();

#pragma unroll
        for (int kk4 = 0; kk4 < 4; ++kk4) {
            float4 a[8];
#pragma unroll
            for (int i = 0; i < 8; ++i)
                a[i] = *(const float4*)(As + (ty * 8 + i) * 16 + kk4 * 4);
#pragma unroll
            for (int q = 0; q < 4; ++q) {
                int kk = kk4 * 4 + q;
                float4 b0 = *(const float4*)(Bs + kk * C + tx * 8);
                float4 b1 = *(const float4*)(Bs + kk * C + tx * 8 + 4);
#pragma unroll
                for (int i = 0; i < 8; ++i) {
                    float av = (q == 0) ? a[i].x : (q == 1) ? a[i].y
                             : (q == 2) ? a[i].z : a[i].w;
                    acc[i][0] += av * b0.x; acc[i][1] += av * b0.y;
                    acc[i][2] += av * b0.z; acc[i][3] += av * b0.w;
                    acc[i][4] += av * b1.x; acc[i][5] += av * b1.y;
                    acc[i][6] += av * b1.z; acc[i][7] += av * b1.w;
                }
            }
        }
        __syncthreads();
    }

    // epilogue: affine-folded BN (+ optional Mish), vectorized stores
#pragma unroll
    for (int i = 0; i < 8; ++i) {
        int r = row0 + ty * 8 + i;
        if (r >= N_NODES) continue;
#pragma unroll
        for (int j4 = 0; j4 < 2; ++j4) {
            float4 o;
            float* op = &o.x;
#pragma unroll
            for (int q = 0; q < 4; ++q) {
                int c = tx * 8 + j4 * 4 + q;
                float v = acc[i][j4 * 4 + q] * s_sc[c] + s_off[c];
                if (apply_mish) {
                    float sp = (v > 20.f) ? v : log1pf(expf(v));
                    v = v * tanhf(sp);
                }
                op[q] = v;
            }
            *(float4*)(out + (size_t)r * C + tx * 8 + j4 * 4) = o;
        }
    }
}

// ---------------- host launcher (graph-capturable: kernel launches only) ----------------
extern "C" void kernel_launch(void* const* d_in, const int* in_sizes, int n_in,
                              void* d_out, int out_size) {
    const float* x  = (const float*)d_in[0];
    const void*  ei = d_in[1];
    const float* Wl = (const float*)d_in[2];
    const float* bl = (const float*)d_in[3];
    const float* Wr = (const float*)d_in[4];
    const float* ga = (const float*)d_in[5];
    const float* be = (const float*)d_in[6];
    const float* rm = (const float*)d_in[7];
    const float* rv = (const float*)d_in[8];
    float* out = (float*)d_out;

    int E = in_sizes[1] / 2;

    int zb = (int)(((size_t)N_NODES * C / 4 + 255) / 256);
    int sb = (int)(((size_t)E * 32 + 255) / 256);
    int gb = (N_NODES + 127) / 128;

    detect_kernel<<<1, 1>>>(ei);

    // layer 0: in = x (sel 0), out = g_h0 (sel 1)
    zero_kernel<<<zb, 256>>>(1);
    scatter_kernel<<<sb, 256>>>(x, 0, ei, E, 1);
    sage_gemm_kernel<<<gb, 256>>>(x, 0, nullptr, 1,
                                  Wl + 0 * C * C, bl + 0 * C, Wr + 0 * C * C,
                                  ga + 0 * C, be + 0 * C, rm + 0 * C, rv + 0 * C, 1);

    // layer 1: in = g_h0 (sel 1), out = g_h1 (sel 2)
    zero_kernel<<<zb, 256>>>(0);
    scatter_kernel<<<sb, 256>>>(nullptr, 1, ei, E, 0);
    sage_gemm_kernel<<<gb, 256>>>(nullptr, 1, nullptr, 2,
                                  Wl + 1 * C * C, bl + 1 * C, Wr + 1 * C * C,
                                  ga + 1 * C, be + 1 * C, rm + 1 * C, rv + 1 * C, 1);

    // layer 2: in = g_h1 (sel 2), out = d_out (sel 0), no Mish
    zero_kernel<<<zb, 256>>>(0);
    scatter_kernel<<<sb, 256>>>(nullptr, 2, ei, E, 0);
    sage_gemm_kernel<<<gb, 256>>>(nullptr, 2, out, 0,
                                  Wl + 2 * C * C, bl + 2 * C, Wr + 2 * C * C,
                                  ga + 2 * C, be + 2 * C, rm + 2 * C, rv + 2 * C, 0);
}

// round 4
// speedup vs baseline: 1.8354x; 1.8354x over previous
#include <cuda_runtime.h>
#include <math.h>

#define N_NODES 100000
#define C 128
#define BN_EPS 1e-5f
#define MAX_E 1600000
#define SCAN_B 512
#define SCAN_NB ((N_NODES + SCAN_B - 1) / SCAN_B)   // 196

// ---------------- persistent device scratch (no allocations; 16B-aligned) ----------------
__device__ float4 g_agg4[(size_t)N_NODES * C / 4];   // mean-aggregated features
__device__ float4 g_h0_4[(size_t)N_NODES * C / 4];   // layer ping
__device__ float4 g_h1_4[(size_t)N_NODES * C / 4];   // layer pong
__device__ int    g_deg[N_NODES];
__device__ int    g_rowptr[N_NODES + 1];
__device__ int    g_cursor[N_NODES];
__device__ float  g_inv[N_NODES];
__device__ int    g_esrc[MAX_E];
__device__ int    g_boff[SCAN_NB + 1];
__device__ int    g_is64;

// ---------------- detect edge_index dtype (int64 vs int32) ----------------
__global__ void detect_kernel(const void* __restrict__ ei) {
    const long long* p64 = (const long long*)ei;
    int ok = 1;
    for (int i = 0; i < 64; ++i) {
        long long v = p64[i];
        if (v < 0 || v >= N_NODES) { ok = 0; break; }
    }
    g_is64 = ok;
}

__device__ __forceinline__ int load_idx(const void* ei, size_t i) {
    return g_is64 ? (int)((const long long*)ei)[i] : ((const int*)ei)[i];
}

// ---------------- CSR build ----------------
__global__ void zero_deg_kernel() {
    int i = blockIdx.x * blockDim.x + threadIdx.x;
    if (i < N_NODES) g_deg[i] = 0;
}

__global__ void hist_kernel(const void* __restrict__ ei, int E) {
    int e = blockIdx.x * blockDim.x + threadIdx.x;
    if (e >= E) return;
    int d = load_idx(ei, (size_t)E + e);
    if ((unsigned)d < N_NODES) atomicAdd(&g_deg[d], 1);
}

__global__ void bsum_kernel() {
    __shared__ int sh[SCAN_B];
    int i = blockIdx.x * SCAN_B + threadIdx.x;
    sh[threadIdx.x] = (i < N_NODES) ? g_deg[i] : 0;
    __syncthreads();
    for (int s = SCAN_B / 2; s > 0; s >>= 1) {
        if (threadIdx.x < s) sh[threadIdx.x] += sh[threadIdx.x + s];
        __syncthreads();
    }
    if (threadIdx.x == 0) g_boff[blockIdx.x] = sh[0];
}

__global__ void scan_boff_kernel() {
    // single thread: exclusive scan of SCAN_NB block sums (196 values)
    if (threadIdx.x == 0 && blockIdx.x == 0) {
        int acc = 0;
        for (int b = 0; b < SCAN_NB; ++b) {
            int v = g_boff[b];
            g_boff[b] = acc;
            acc += v;
        }
        g_boff[SCAN_NB] = acc;
    }
}

__global__ void rowptr_kernel(int E) {
    __shared__ int sh[SCAN_B];
    int i = blockIdx.x * SCAN_B + threadIdx.x;
    int d = (i < N_NODES) ? g_deg[i] : 0;
    sh[threadIdx.x] = d;
    __syncthreads();
    // Hillis-Steele inclusive scan
    for (int s = 1; s < SCAN_B; s <<= 1) {
        int v = (threadIdx.x >= s) ? sh[threadIdx.x - s] : 0;
        __syncthreads();
        sh[threadIdx.x] += v;
        __syncthreads();
    }
    if (i < N_NODES) {
        int start = g_boff[blockIdx.x] + sh[threadIdx.x] - d;  // exclusive
        g_rowptr[i] = start;
        g_cursor[i] = start;
        g_inv[i] = 1.0f / fmaxf((float)d, 1.0f);
        if (i == N_NODES - 1) g_rowptr[N_NODES] = g_boff[SCAN_NB];
    }
}

__global__ void fill_kernel(const void* __restrict__ ei, int E) {
    int e = blockIdx.x * blockDim.x + threadIdx.x;
    if (e >= E) return;
    int s = load_idx(ei, e);
    int d = load_idx(ei, (size_t)E + e);
    if ((unsigned)s >= N_NODES || (unsigned)d >= N_NODES) return;
    int slot = atomicAdd(&g_cursor[d], 1);
    if (slot < MAX_E) g_esrc[slot] = s;
}

// ---------------- gather-aggregate: warp per node, writes mean directly ----------------
__global__ __launch_bounds__(256)
void gather_kernel(const float4* __restrict__ x_ext, int in_sel) {
    const float4* x = (in_sel == 0) ? x_ext : (in_sel == 1 ? g_h0_4 : g_h1_4);
    int warp = (blockIdx.x * blockDim.x + threadIdx.x) >> 5;
    int lane = threadIdx.x & 31;
    if (warp >= N_NODES) return;
    int beg = g_rowptr[warp];
    int end = g_rowptr[warp + 1];

    float4 a0 = make_float4(0.f, 0.f, 0.f, 0.f);
    float4 a1 = a0, a2 = a0, a3 = a0;
    int e = beg;
    for (; e + 4 <= end; e += 4) {
        int s0 = g_esrc[e], s1 = g_esrc[e + 1], s2 = g_esrc[e + 2], s3 = g_esrc[e + 3];
        float4 v0 = x[(size_t)s0 * 32 + lane];
        float4 v1 = x[(size_t)s1 * 32 + lane];
        float4 v2 = x[(size_t)s2 * 32 + lane];
        float4 v3 = x[(size_t)s3 * 32 + lane];
        a0.x += v0.x; a0.y += v0.y; a0.z += v0.z; a0.w += v0.w;
        a1.x += v1.x; a1.y += v1.y; a1.z += v1.z; a1.w += v1.w;
        a2.x += v2.x; a2.y += v2.y; a2.z += v2.z; a2.w += v2.w;
        a3.x += v3.x; a3.y += v3.y; a3.z += v3.z; a3.w += v3.w;
    }
    for (; e < end; ++e) {
        int s0 = g_esrc[e];
        float4 v0 = x[(size_t)s0 * 32 + lane];
        a0.x += v0.x; a0.y += v0.y; a0.z += v0.z; a0.w += v0.w;
    }
    a0.x += a1.x + a2.x + a3.x;
    a0.y += a1.y + a2.y + a3.y;
    a0.z += a1.z + a2.z + a3.z;
    a0.w += a1.w + a2.w + a3.w;
    float iv = g_inv[warp];
    a0.x *= iv; a0.y *= iv; a0.z *= iv; a0.w *= iv;
    g_agg4[(size_t)warp * 32 + lane] = a0;
}

// ---------------- fused: out = mean @ Wl + bl + hin @ Wr, then BN (+ Mish) ----------------
// CTA: 256 threads, 128x128 output tile, K = 256 in chunks of 16, 8x8 per-thread micro-tile.
__global__ __launch_bounds__(256)
void sage_gemm_kernel(const float* __restrict__ hin_ext, int in_sel,
                      float* __restrict__ out_ext, int out_sel,
                      const float* __restrict__ Wl, const float* __restrict__ bl,
                      const float* __restrict__ Wr,
                      const float* __restrict__ gamma, const float* __restrict__ beta,
                      const float* __restrict__ rmean, const float* __restrict__ rvar,
                      int apply_mish) {
    const float* hin = (in_sel == 0) ? hin_ext : (in_sel == 1 ? (const float*)g_h0_4
                                                              : (const float*)g_h1_4);
    float* out = (out_sel == 0) ? out_ext : (out_sel == 1 ? (float*)g_h0_4
                                                          : (float*)g_h1_4);

    __shared__ float As[128 * 16];   // A tile, [m][k] row-major
    __shared__ float Bs[16 * 128];   // W tile, [k][n] row-major
    __shared__ float s_sc[128];
    __shared__ float s_off[128];

    int t = threadIdx.x;
    int row0 = blockIdx.x * 128;

    if (t < 128) {
        float sc = gamma[t] * rsqrtf(rvar[t] + BN_EPS);
        s_sc[t] = sc;
        s_off[t] = (bl[t] - rmean[t]) * sc + beta[t];
    }
    __syncthreads();

    int tx = t & 15;   // col group: cols tx*8 .. tx*8+7
    int ty = t >> 4;   // row group: rows ty*8 .. ty*8+7

    float acc[8][8];
#pragma unroll
    for (int i = 0; i < 8; ++i)
#pragma unroll
        for (int j = 0; j < 8; ++j) acc[i][j] = 0.f;

    int a_m = t >> 2;   // 0..63 (and +64)
    int a_c = t & 3;    // float4 column within 16-wide k chunk
    int b_k = t >> 5;   // 0..7 (and +8)
    int b_c = t & 31;   // float4 column within 128-wide row

    for (int kc = 0; kc < 2 * C; kc += 16) {
        bool isAgg = (kc < C);
        const float* Abase = isAgg ? (const float*)g_agg4 : hin;
        const float* Wb    = isAgg ? Wl : Wr;
        int koff = isAgg ? kc : (kc - C);

#pragma unroll
        for (int h = 0; h < 2; ++h) {
            int m = a_m + h * 64;
            int r = row0 + m;
            float4 v = make_float4(0.f, 0.f, 0.f, 0.f);
            if (r < N_NODES)
                v = *(const float4*)(Abase + (size_t)r * C + koff + a_c * 4);
            *(float4*)(As + m * 16 + a_c * 4) = v;
        }
#pragma unroll
        for (int h = 0; h < 2; ++h) {
            int k = b_k + h * 8;
            float4 v = *(const float4*)(Wb + (size_t)(koff + k) * C + b_c * 4);
            *(float4*)(Bs + k * C + b_c * 4) = v;
        }
        __syncthreads();

#pragma unroll
        for (int kk4 = 0; kk4 < 4; ++kk4) {
            float4 a[8];
#pragma unroll
            for (int i = 0; i < 8; ++i)
                a[i] = *(const float4*)(As + (ty * 8 + i) * 16 + kk4 * 4);
#pragma unroll
            for (int q = 0; q < 4; ++q) {
                int kk = kk4 * 4 + q;
                float4 b0 = *(const float4*)(Bs + kk * C + tx * 8);
                float4 b1 = *(const float4*)(Bs + kk * C + tx * 8 + 4);
#pragma unroll
                for (int i = 0; i < 8; ++i) {
                    float av = (q == 0) ? a[i].x : (q == 1) ? a[i].y
                             : (q == 2) ? a[i].z : a[i].w;
                    acc[i][0] += av * b0.x; acc[i][1] += av * b0.y;
                    acc[i][2] += av * b0.z; acc[i][3] += av * b0.w;
                    acc[i][4] += av * b1.x; acc[i][5] += av * b1.y;
                    acc[i][6] += av * b1.z; acc[i][7] += av * b1.w;
                }
            }
        }
        __syncthreads();
    }

#pragma unroll
    for (int i = 0; i < 8; ++i) {
        int r = row0 + ty * 8 + i;
        if (r >= N_NODES) continue;
#pragma unroll
        for (int j4 = 0; j4 < 2; ++j4) {
            float4 o;
            float* op = &o.x;
#pragma unroll
            for (int q = 0; q < 4; ++q) {
                int c = tx * 8 + j4 * 4 + q;
                float v = acc[i][j4 * 4 + q] * s_sc[c] + s_off[c];
                if (apply_mish) {
                    float sp = (v > 20.f) ? v : log1pf(expf(v));
                    v = v * tanhf(sp);
                }
                op[q] = v;
            }
            *(float4*)(out + (size_t)r * C + tx * 8 + j4 * 4) = o;
        }
    }
}

// ---------------- host launcher (graph-capturable: kernel launches only) ----------------
extern "C" void kernel_launch(void* const* d_in, const int* in_sizes, int n_in,
                              void* d_out, int out_size) {
    const float* x  = (const float*)d_in[0];
    const void*  ei = d_in[1];
    const float* Wl = (const float*)d_in[2];
    const float* bl = (const float*)d_in[3];
    const float* Wr = (const float*)d_in[4];
    const float* ga = (const float*)d_in[5];
    const float* be = (const float*)d_in[6];
    const float* rm = (const float*)d_in[7];
    const float* rv = (const float*)d_in[8];
    float* out = (float*)d_out;

    int E = in_sizes[1] / 2;

    int eb = (E + 255) / 256;
    int nb = (N_NODES + 255) / 256;
    int wb = (N_NODES * 32 + 255) / 256;   // warp-per-node gather
    int gb = (N_NODES + 127) / 128;

    // ---- CSR build (once per launch; dst shared by all 3 layers) ----
    detect_kernel<<<1, 1>>>(ei);
    zero_deg_kernel<<<nb, 256>>>();
    hist_kernel<<<eb, 256>>>(ei, E);
    bsum_kernel<<<SCAN_NB, SCAN_B>>>();
    scan_boff_kernel<<<1, 32>>>();
    rowptr_kernel<<<SCAN_NB, SCAN_B>>>(E);
    fill_kernel<<<eb, 256>>>(ei, E);

    // layer 0: in = x, out = g_h0
    gather_kernel<<<wb, 256>>>((const float4*)x, 0);
    sage_gemm_kernel<<<gb, 256>>>(x, 0, nullptr, 1,
                                  Wl + 0 * C * C, bl + 0 * C, Wr + 0 * C * C,
                                  ga + 0 * C, be + 0 * C, rm + 0 * C, rv + 0 * C, 1);

    // layer 1: in = g_h0, out = g_h1
    gather_kernel<<<wb, 256>>>(nullptr, 1);
    sage_gemm_kernel<<<gb, 256>>>(nullptr, 1, nullptr, 2,
                                  Wl + 1 * C * C, bl + 1 * C, Wr + 1 * C * C,
                                  ga + 1 * C, be + 1 * C, rm + 1 * C, rv + 1 * C, 1);

    // layer 2: in = g_h1, out = d_out, no Mish
    gather_kernel<<<wb, 256>>>(nullptr, 2);
    sage_gemm_kernel<<<gb, 256>>>(nullptr, 2, out, 0,
                                  Wl + 2 * C * C, bl + 2 * C, Wr + 2 * C * C,
                                  ga + 2 * C, be + 2 * C, rm + 2 * C, rv + 2 * C, 0);
}